// round 12
// baseline (speedup 1.0000x reference)
#include <cuda_runtime.h>
#include <cuda_fp16.h>
#include <cstdint>

// ============================================================================
// CrossAttention via fp16-split mma.sync GEMMs (sm_103-safe: no arch-'a' ops).
//   out = softmax((Xq Wq)(Xk Wk)^T over heads) (Xv Wv) Wo + bo
// N=32768, D=512, H=8.
//
// GEMM precision: operands pre-split to fp16 hi|lo.
//   NPASS=3 (Q,K):  Ah*Bh + Al*Bh + Ah*Bl   (~2^-22, softmax-amplified path)
//   NPASS=2 (V,O):  Ah*Bh + Al*Bh           (~2^-12, unamplified)
//
// R10: 4-stage BK=32 cp.async pipeline, ONE __syncthreads per k-iter (SW64
//      swizzle). Weight transposes fused (2 launches) so ncu -s5 profiles the
//      Q GEMM (launch #6).
// ============================================================================

#define NTOK 32768
#define DMODEL 512
#define DHID 4096

// ---------------- scratch (device globals; allocation-free) -----------------
__device__ float g_Q[(size_t)NTOK * DHID];
__device__ float g_K[(size_t)NTOK * DHID];
__device__ float g_V[(size_t)NTOK * DHID];
__device__ __half g_AOs[(size_t)NTOK * 2 * DHID];     // [32768][8192] hi|lo
__device__ __half g_Xq[(size_t)NTOK * 2 * DMODEL];    // [32768][1024] hi|lo
__device__ __half g_Xk[(size_t)NTOK * 2 * DMODEL];
__device__ __half g_Xv[(size_t)NTOK * 2 * DMODEL];
__device__ __half g_Wqs[(size_t)DHID * 2 * DMODEL];   // [4096][1024] K-major hi|lo
__device__ __half g_Wks[(size_t)DHID * 2 * DMODEL];
__device__ __half g_Wvs[(size_t)DHID * 2 * DMODEL];
__device__ __half g_Wos[(size_t)DMODEL * 2 * DHID];   // [512][8192]  K-major hi|lo

// ---------------------------- PTX helpers -----------------------------------
__device__ __forceinline__ uint32_t smem_u32(const void* p) {
    uint32_t a;
    asm("{ .reg .u64 t; cvta.to.shared.u64 t, %1; cvt.u32.u64 %0, t; }" : "=r"(a) : "l"(p));
    return a;
}
// SW64 swizzle: 64-byte rows, atom = 8 rows x 64B. Conflict-free for both
// cp.async 16B stores and ldmatrix 8x16B row gathers.
#define SWZ64(x) ((x) ^ (((x) >> 3) & 0x30))

__device__ __forceinline__ void cp16(uint32_t dst, const void* src) {
    asm volatile("cp.async.cg.shared.global [%0], [%1], 16;\n" :: "r"(dst), "l"(src));
}
__device__ __forceinline__ void cp_commit() { asm volatile("cp.async.commit_group;\n"); }
template<int Ng> __device__ __forceinline__ void cp_wait() {
    asm volatile("cp.async.wait_group %0;\n" :: "n"(Ng));
}

__device__ __forceinline__ void ldmx4(uint32_t* r, uint32_t addr) {
    asm volatile("ldmatrix.sync.aligned.m8n8.x4.shared.b16 {%0,%1,%2,%3}, [%4];"
                 : "=r"(r[0]), "=r"(r[1]), "=r"(r[2]), "=r"(r[3]) : "r"(addr));
}

__device__ __forceinline__ void mma_f16(float* d, const uint32_t* a, const uint32_t* b) {
    asm volatile(
        "mma.sync.aligned.m16n8k16.row.col.f32.f16.f16.f32 "
        "{%0,%1,%2,%3}, {%4,%5,%6,%7}, {%8,%9}, {%0,%1,%2,%3};\n"
        : "+f"(d[0]), "+f"(d[1]), "+f"(d[2]), "+f"(d[3])
        : "r"(a[0]), "r"(a[1]), "r"(a[2]), "r"(a[3]), "r"(b[0]), "r"(b[1]));
}

// ---------------------------------------------------------------------------
// GEMM: C[M,N] = A @ B^T (split fp16), A:[rows][lda] hi|lo (lo at +kaLo within
// row), B:[N rows][ldb] K-major hi|lo. CTA tile 256x128, BK=32 (64B SW64 rows).
// 4-stage cp.async pipeline, one __syncthreads per k-iter.
// 256 threads = 8 warps (4x2), warp tile 64x64.
// ---------------------------------------------------------------------------
constexpr int ATILE = 256 * 64;  // 16 KB: one 256x32 fp16 A operand tile
constexpr int BTILE = 128 * 64;  //  8 KB: one 128x32 fp16 B operand tile
constexpr int NSTAGE = 4;

template<int NPASS>
__global__ __launch_bounds__(256)
void gemm_split_hmma(const __half* __restrict__ A, int lda, int kaLo,
                     const __half* __restrict__ B, int ldb, int kbLo,
                     float* __restrict__ C, int ldc,
                     const float* __restrict__ bias, int KT)
{
    constexpr int STAGE = 2 * ATILE + (NPASS == 3 ? 2 : 1) * BTILE; // Ah,Al,Bh[,Bl]
    extern __shared__ char smraw[];
    const uint32_t base = (smem_u32(smraw) + 1023u) & ~1023u;

    const int tid = threadIdx.x, wid = tid >> 5, lane = tid & 31;
    const int mBase = blockIdx.y * 256, nBase = blockIdx.x * 128;

    const int chunk = tid & 3;       // 16B chunk within a 64B row
    const int rbase = tid >> 2;      // 0..63

    auto issue = [&](int t, int slot) {
        const int kk = t * 32;
        const uint32_t bb = base + slot * STAGE;
        const __half* Ap = A + (size_t)mBase * lda + kk + chunk * 8;
        const __half* Bp = B + (size_t)nBase * ldb + kk + chunk * 8;
        #pragma unroll
        for (int i = 0; i < 4; i++) {
            const int row = rbase + i * 64;
            const uint32_t so = SWZ64((uint32_t)(row * 64 + chunk * 16));
            cp16(bb + so,         Ap + (size_t)row * lda);          // Ah
            cp16(bb + ATILE + so, Ap + kaLo + (size_t)row * lda);   // Al
        }
        #pragma unroll
        for (int i = 0; i < 2; i++) {
            const int row = rbase + i * 64;
            const uint32_t so = SWZ64((uint32_t)(row * 64 + chunk * 16));
            cp16(bb + 2 * ATILE + so, Bp + (size_t)row * ldb);      // Bh
            if (NPASS == 3)
                cp16(bb + 2 * ATILE + BTILE + so, Bp + kbLo + (size_t)row * ldb); // Bl
        }
        cp_commit();
    };

    float acc[4][8][4];
    #pragma unroll
    for (int i = 0; i < 4; i++)
        #pragma unroll
        for (int j = 0; j < 8; j++)
            #pragma unroll
            for (int l = 0; l < 4; l++) acc[i][j][l] = 0.f;

    const int g = lane >> 2, tq = lane & 3;
    const int wm = (wid >> 1) * 64, wn = (wid & 1) * 64;
    const int rowSel = lane & 15;
    const uint32_t colB = (uint32_t)((lane >> 4) * 16);  // byte offset in row

    issue(0, 0);
    issue(1, 1);
    issue(2, 2);

    for (int t = 0; t < KT; t++) {
        const int slot = t & 3;
        cp_wait<2>();        // stage t resident (<=2 younger groups pending)
        __syncthreads();     // cross-warp visibility + overwrite protection
        if (t + 3 < KT) issue(t + 3, (t + 3) & 3);

        const uint32_t bb = base + slot * STAGE;
        #pragma unroll
        for (int ks = 0; ks < 2; ks++) {
            const uint32_t kbyte = (uint32_t)(ks * 32) + colB;

            uint32_t ah[4][4], al[4][4];
            #pragma unroll
            for (int mf = 0; mf < 4; mf++) {
                const uint32_t ro = (uint32_t)((wm + mf * 16 + rowSel) * 64);
                const uint32_t ad = bb + SWZ64(ro + kbyte);
                ldmx4(ah[mf], ad);
                ldmx4(al[mf], ad + ATILE);
            }

            uint32_t bh[8][2], bl[8][2];
            #pragma unroll
            for (int nb = 0; nb < 4; nb++) {
                const uint32_t ro = (uint32_t)((wn + nb * 16 + rowSel) * 64);
                const uint32_t ad = bb + 2 * ATILE + SWZ64(ro + kbyte);
                uint32_t r[4];
                ldmx4(r, ad);
                bh[nb * 2][0] = r[0]; bh[nb * 2][1] = r[2];
                bh[nb * 2 + 1][0] = r[1]; bh[nb * 2 + 1][1] = r[3];
                if (NPASS == 3) {
                    uint32_t s[4];
                    ldmx4(s, ad + BTILE);
                    bl[nb * 2][0] = s[0]; bl[nb * 2][1] = s[2];
                    bl[nb * 2 + 1][0] = s[1]; bl[nb * 2 + 1][1] = s[3];
                }
            }

            #pragma unroll
            for (int mf = 0; mf < 4; mf++)
                #pragma unroll
                for (int nf = 0; nf < 8; nf++) {
                    mma_f16(acc[mf][nf], ah[mf], bh[nf]);
                    mma_f16(acc[mf][nf], al[mf], bh[nf]);
                    if (NPASS == 3) mma_f16(acc[mf][nf], ah[mf], bl[nf]);
                }
        }
    }

    // epilogue: direct float2 stores; each STG fills complete 32B sectors.
    const bool hasB = (bias != nullptr);
    #pragma unroll
    for (int mf = 0; mf < 4; mf++) {
        const int row = mBase + wm + mf * 16 + g;
        #pragma unroll
        for (int nf = 0; nf < 8; nf++) {
            const int col = nBase + wn + nf * 8 + 2 * tq;
            const float b0 = hasB ? bias[col] : 0.f;
            const float b1 = hasB ? bias[col + 1] : 0.f;
            *(float2*)&C[(size_t)row * ldc + col] =
                make_float2(acc[mf][nf][0] + b0, acc[mf][nf][1] + b1);
            *(float2*)&C[(size_t)(row + 8) * ldc + col] =
                make_float2(acc[mf][nf][2] + b0, acc[mf][nf][3] + b1);
        }
    }
}

// ---------------------------------------------------------------------------
// Converters
// ---------------------------------------------------------------------------
__global__ __launch_bounds__(256)
void act_split_h(const float* __restrict__ X, __half* __restrict__ Y)
{
    const int idx = blockIdx.x * 256 + threadIdx.x;  // one float4 of a 512-col row
    const int row = idx >> 7, c4 = idx & 127;
    const float4 v = ((const float4*)X)[idx];
    float f[4] = { v.x, v.y, v.z, v.w };
    __half h[4], l[4];
    #pragma unroll
    for (int i = 0; i < 4; i++) {
        h[i] = __float2half_rn(f[i]);
        l[i] = __float2half_rn(f[i] - __half2float(h[i]));
    }
    const size_t o = (size_t)row * 1024 + c4 * 4;
    __half2* ph = (__half2*)(Y + o);
    ph[0] = __halves2half2(h[0], h[1]);
    ph[1] = __halves2half2(h[2], h[3]);
    __half2* pl = (__half2*)(Y + o + DMODEL);
    pl[0] = __halves2half2(l[0], l[1]);
    pl[1] = __halves2half2(l[2], l[3]);
}

// Batched transpose+split for Wq/Wk/Wv (blockIdx.z selects tensor).
__global__ __launch_bounds__(256)
void wtrans_split_qkv(const float* __restrict__ W0, __half* __restrict__ Y0,
                      const float* __restrict__ W1, __half* __restrict__ Y1,
                      const float* __restrict__ W2, __half* __restrict__ Y2)
{
    const float* W = (blockIdx.z == 0) ? W0 : (blockIdx.z == 1) ? W1 : W2;
    __half*      Y = (blockIdx.z == 0) ? Y0 : (blockIdx.z == 1) ? Y1 : Y2;
    const int Kin = DMODEL, Nin = DHID, ldo = 2 * DMODEL;

    __shared__ float t[32][33];
    const int n  = blockIdx.x * 32 + threadIdx.x;
    const int k0 = blockIdx.y * 32;
    #pragma unroll
    for (int i = 0; i < 4; i++)
        t[threadIdx.y + i * 8][threadIdx.x] = W[(size_t)(k0 + threadIdx.y + i * 8) * Nin + n];
    __syncthreads();
    const int kc = k0 + threadIdx.x;
    #pragma unroll
    for (int i = 0; i < 4; i++) {
        const int nr = blockIdx.x * 32 + threadIdx.y + i * 8;
        const float v = t[threadIdx.x][threadIdx.y + i * 8];
        const __half hi = __float2half_rn(v);
        const __half lo = __float2half_rn(v - __half2float(hi));
        Y[(size_t)nr * ldo + kc]       = hi;
        Y[(size_t)nr * ldo + Kin + kc] = lo;
    }
}

__global__ __launch_bounds__(256)
void wtrans_split_h(const float* __restrict__ W, __half* __restrict__ Y,
                    int Kin, int Nin, int ldo)
{
    __shared__ float t[32][33];
    const int n  = blockIdx.x * 32 + threadIdx.x;
    const int k0 = blockIdx.y * 32;
    #pragma unroll
    for (int i = 0; i < 4; i++)
        t[threadIdx.y + i * 8][threadIdx.x] = W[(size_t)(k0 + threadIdx.y + i * 8) * Nin + n];
    __syncthreads();
    const int kc = k0 + threadIdx.x;
    #pragma unroll
    for (int i = 0; i < 4; i++) {
        const int nr = blockIdx.x * 32 + threadIdx.y + i * 8;
        const float v = t[threadIdx.x][threadIdx.y + i * 8];
        const __half hi = __float2half_rn(v);
        const __half lo = __float2half_rn(v - __half2float(hi));
        Y[(size_t)nr * ldo + kc]       = hi;
        Y[(size_t)nr * ldo + Kin + kc] = lo;
    }
}

// ---------------------------------------------------------------------------
// Per-token attention (8x8 over heads); writes AO as split fp16 [hi|lo].
// ---------------------------------------------------------------------------
__global__ __launch_bounds__(128)
void attn_kernel()
{
    const int n = blockIdx.x;
    const int tid = threadIdx.x;
    const size_t base = (size_t)n * DHID;
    const size_t b2 = (size_t)n * (2 * DHID);

    __shared__ float red[4][64];
    __shared__ float Sf[64];
    __shared__ float P[64];

    float q[8][4], k[8][4];
    #pragma unroll
    for (int h = 0; h < 8; h++)
        #pragma unroll
        for (int j = 0; j < 4; j++) {
            const int d = tid + j * 128;
            q[h][j] = g_Q[base + h * DMODEL + d];
            k[h][j] = g_K[base + h * DMODEL + d];
        }

    float s[64];
    #pragma unroll
    for (int h = 0; h < 8; h++)
        #pragma unroll
        for (int gg = 0; gg < 8; gg++) {
            float a = 0.f;
            #pragma unroll
            for (int j = 0; j < 4; j++) a += q[h][j] * k[gg][j];
            s[h * 8 + gg] = a;
        }

    const int lane = tid & 31, w = tid >> 5;
    #pragma unroll
    for (int i = 0; i < 64; i++) {
        float v = s[i];
        v += __shfl_down_sync(0xffffffffu, v, 16);
        v += __shfl_down_sync(0xffffffffu, v, 8);
        v += __shfl_down_sync(0xffffffffu, v, 4);
        v += __shfl_down_sync(0xffffffffu, v, 2);
        v += __shfl_down_sync(0xffffffffu, v, 1);
        if (lane == 0) red[w][i] = v;
    }
    __syncthreads();
    if (tid < 64) Sf[tid] = red[0][tid] + red[1][tid] + red[2][tid] + red[3][tid];
    __syncthreads();
    if (tid < 8) {
        float m = -1e30f;
        #pragma unroll
        for (int gg = 0; gg < 8; gg++) m = fmaxf(m, Sf[tid * 8 + gg]);
        float e[8], sum = 0.f;
        #pragma unroll
        for (int gg = 0; gg < 8; gg++) { e[gg] = expf(Sf[tid * 8 + gg] - m); sum += e[gg]; }
        const float inv = 1.f / sum;
        #pragma unroll
        for (int gg = 0; gg < 8; gg++) P[tid * 8 + gg] = e[gg] * inv;
    }
    __syncthreads();

    float vv[8][4];
    #pragma unroll
    for (int h = 0; h < 8; h++)
        #pragma unroll
        for (int j = 0; j < 4; j++)
            vv[h][j] = g_V[base + h * DMODEL + tid + j * 128];

    #pragma unroll
    for (int h = 0; h < 8; h++) {
        #pragma unroll
        for (int j = 0; j < 4; j++) {
            float o = 0.f;
            #pragma unroll
            for (int gg = 0; gg < 8; gg++) o += P[h * 8 + gg] * vv[gg][j];
            const int d = h * DMODEL + tid + j * 128;
            const __half hi = __float2half_rn(o);
            const __half lo = __float2half_rn(o - __half2float(hi));
            g_AOs[b2 + d]        = hi;
            g_AOs[b2 + DHID + d] = lo;
        }
    }
}

// ---------------------------------------------------------------------------
// launch
// ---------------------------------------------------------------------------
extern "C" void kernel_launch(void* const* d_in, const int* in_sizes, int n_in,
                              void* d_out, int out_size)
{
    const float* queries = (const float*)d_in[0];
    const float* keys    = (const float*)d_in[1];
    const float* values  = (const float*)d_in[2];
    const float* Wq      = (const float*)d_in[3];
    const float* Wk      = (const float*)d_in[4];
    const float* Wv      = (const float*)d_in[5];
    const float* Wo      = (const float*)d_in[6];
    const float* bo      = (const float*)d_in[7];
    float* out = (float*)d_out;

    float *Qp, *Kp, *Vp;
    __half *Xq, *Xk, *Xv, *Wqs, *Wks, *Wvs, *Wos, *AOs;
    cudaGetSymbolAddress((void**)&Qp,  g_Q);
    cudaGetSymbolAddress((void**)&Kp,  g_K);
    cudaGetSymbolAddress((void**)&Vp,  g_V);
    cudaGetSymbolAddress((void**)&Xq,  g_Xq);
    cudaGetSymbolAddress((void**)&Xk,  g_Xk);
    cudaGetSymbolAddress((void**)&Xv,  g_Xv);
    cudaGetSymbolAddress((void**)&Wqs, g_Wqs);
    cudaGetSymbolAddress((void**)&Wks, g_Wks);
    cudaGetSymbolAddress((void**)&Wvs, g_Wvs);
    cudaGetSymbolAddress((void**)&Wos, g_Wos);
    cudaGetSymbolAddress((void**)&AOs, g_AOs);

    const int SM3 = 1024 + NSTAGE * (2 * ATILE + 2 * BTILE);  // ~193 KB
    const int SM2 = 1024 + NSTAGE * (2 * ATILE + 1 * BTILE);  // ~161 KB
    cudaFuncSetAttribute(gemm_split_hmma<3>,
                         cudaFuncAttributeMaxDynamicSharedMemorySize, SM3);
    cudaFuncSetAttribute(gemm_split_hmma<2>,
                         cudaFuncAttributeMaxDynamicSharedMemorySize, SM2);

    // 1) split converts — exactly 5 launches before the first GEMM so that
    //    ncu (-s 5 -c 1) profiles the 3-pass Q GEMM.
    act_split_h<<<16384, 256>>>(queries, Xq);                                 // 1
    act_split_h<<<16384, 256>>>(keys,    Xk);                                 // 2
    act_split_h<<<16384, 256>>>(values,  Xv);                                 // 3
    wtrans_split_qkv<<<dim3(DHID / 32, DMODEL / 32, 3), dim3(32, 8)>>>(       // 4
        Wq, Wqs, Wk, Wks, Wv, Wvs);
    wtrans_split_h<<<dim3(DMODEL / 32, DHID / 32), dim3(32, 8)>>>(            // 5
        Wo, Wos, DHID, DMODEL, 2 * DHID);

    // 2) projections
    dim3 gProj(DHID / 128, NTOK / 256);   // (32, 128)
    gemm_split_hmma<3><<<gProj, 256, SM3>>>(Xq, 2 * DMODEL, DMODEL, Wqs, 2 * DMODEL, DMODEL,
                                            Qp, DHID, nullptr, DMODEL / 32);  // 6 (profiled)
    gemm_split_hmma<3><<<gProj, 256, SM3>>>(Xk, 2 * DMODEL, DMODEL, Wks, 2 * DMODEL, DMODEL,
                                            Kp, DHID, nullptr, DMODEL / 32);
    gemm_split_hmma<2><<<gProj, 256, SM2>>>(Xv, 2 * DMODEL, DMODEL, Wvs, 2 * DMODEL, DMODEL,
                                            Vp, DHID, nullptr, DMODEL / 32);

    // 3) per-token attention -> split fp16 AO
    attn_kernel<<<NTOK, 128>>>();

    // 4) output projection + bias
    dim3 gOut(DMODEL / 128, NTOK / 256);  // (4, 128)
    gemm_split_hmma<2><<<gOut, 256, SM2>>>(AOs, 2 * DHID, DHID, Wos, 2 * DHID, DHID,
                                           out, DMODEL, bo, DHID / 32);
}

// round 13
// speedup vs baseline: 1.1039x; 1.1039x over previous
#include <cuda_runtime.h>
#include <cuda_fp16.h>
#include <cstdint>

// ============================================================================
// CrossAttention via fp16-split mma.sync GEMMs (sm_103-safe: no arch-'a' ops).
//   out = softmax((Xq Wq)(Xk Wk)^T over heads) (Xv Wv) Wo + bo
// N=32768, D=512, H=8.
//
// GEMM precision: operands pre-split to fp16 hi|lo.
//   NPASS=3 (Q,K):  Ah*Bh + Al*Bh + Ah*Bl   (~2^-22, softmax-amplified path)
//   NPASS=2 (V,O):  Ah*Bh + Al*Bh           (~2^-12, unamplified)
//
// R12: occupancy play. CTA 128x128, BK=32, 3-stage cp.async, smem 97KB/73KB
//      -> 2 CTAs/SM (16 warps/SM, 4/SMSP) to cover barrier/LDSM bubbles.
//      __launch_bounds__(256,2); B-fragments consumed in nf-halves to keep
//      live regs ~112 < 128.
// ============================================================================

#define NTOK 32768
#define DMODEL 512
#define DHID 4096

// ---------------- scratch (device globals; allocation-free) -----------------
__device__ float g_Q[(size_t)NTOK * DHID];
__device__ float g_K[(size_t)NTOK * DHID];
__device__ float g_V[(size_t)NTOK * DHID];
__device__ __half g_AOs[(size_t)NTOK * 2 * DHID];     // [32768][8192] hi|lo
__device__ __half g_Xq[(size_t)NTOK * 2 * DMODEL];    // [32768][1024] hi|lo
__device__ __half g_Xk[(size_t)NTOK * 2 * DMODEL];
__device__ __half g_Xv[(size_t)NTOK * 2 * DMODEL];
__device__ __half g_Wqs[(size_t)DHID * 2 * DMODEL];   // [4096][1024] K-major hi|lo
__device__ __half g_Wks[(size_t)DHID * 2 * DMODEL];
__device__ __half g_Wvs[(size_t)DHID * 2 * DMODEL];
__device__ __half g_Wos[(size_t)DMODEL * 2 * DHID];   // [512][8192]  K-major hi|lo

// ---------------------------- PTX helpers -----------------------------------
__device__ __forceinline__ uint32_t smem_u32(const void* p) {
    uint32_t a;
    asm("{ .reg .u64 t; cvta.to.shared.u64 t, %1; cvt.u32.u64 %0, t; }" : "=r"(a) : "l"(p));
    return a;
}
// SW64 swizzle: 64-byte rows, atom = 8 rows x 64B. Conflict-free for both
// cp.async 16B stores and ldmatrix 8x16B row gathers.
#define SWZ64(x) ((x) ^ (((x) >> 3) & 0x30))

__device__ __forceinline__ void cp16(uint32_t dst, const void* src) {
    asm volatile("cp.async.cg.shared.global [%0], [%1], 16;\n" :: "r"(dst), "l"(src));
}
__device__ __forceinline__ void cp_commit() { asm volatile("cp.async.commit_group;\n"); }
template<int Ng> __device__ __forceinline__ void cp_wait() {
    asm volatile("cp.async.wait_group %0;\n" :: "n"(Ng));
}

__device__ __forceinline__ void ldmx4(uint32_t* r, uint32_t addr) {
    asm volatile("ldmatrix.sync.aligned.m8n8.x4.shared.b16 {%0,%1,%2,%3}, [%4];"
                 : "=r"(r[0]), "=r"(r[1]), "=r"(r[2]), "=r"(r[3]) : "r"(addr));
}

__device__ __forceinline__ void mma_f16(float* d, const uint32_t* a, const uint32_t* b) {
    asm volatile(
        "mma.sync.aligned.m16n8k16.row.col.f32.f16.f16.f32 "
        "{%0,%1,%2,%3}, {%4,%5,%6,%7}, {%8,%9}, {%0,%1,%2,%3};\n"
        : "+f"(d[0]), "+f"(d[1]), "+f"(d[2]), "+f"(d[3])
        : "r"(a[0]), "r"(a[1]), "r"(a[2]), "r"(a[3]), "r"(b[0]), "r"(b[1]));
}

// ---------------------------------------------------------------------------
// GEMM: C[M,N] = A @ B^T (split fp16), A:[rows][lda] hi|lo (lo at +kaLo within
// row), B:[N rows][ldb] K-major hi|lo. CTA tile 128x128, BK=32 (64B SW64 rows),
// 3-stage cp.async pipeline, 256 threads = 8 warps (4x2), warp tile 32x64.
// smem <= 97KB so 2 CTAs co-reside per SM.
// ---------------------------------------------------------------------------
constexpr int OPTILE = 128 * 64;   // 8 KB: one 128x32 fp16 operand tile
constexpr int NSTAGE = 3;

template<int NPASS>
__global__ __launch_bounds__(256, 2)
void gemm_split_hmma(const __half* __restrict__ A, int lda, int kaLo,
                     const __half* __restrict__ B, int ldb, int kbLo,
                     float* __restrict__ C, int ldc,
                     const float* __restrict__ bias, int KT)
{
    constexpr int NT = (NPASS == 3) ? 4 : 3;      // Ah, Al, Bh[, Bl]
    constexpr int STAGE = NT * OPTILE;
    extern __shared__ char smraw[];
    const uint32_t base = (smem_u32(smraw) + 1023u) & ~1023u;

    const int tid = threadIdx.x, wid = tid >> 5, lane = tid & 31;
    const int mBase = blockIdx.y * 128, nBase = blockIdx.x * 128;

    const int chunk = tid & 3;       // 16B chunk within a 64B row
    const int rbase = tid >> 2;      // 0..63

    auto issue = [&](int t, int slot) {
        const int kk = t * 32;
        const uint32_t bb = base + slot * STAGE;
        const __half* Ap = A + (size_t)mBase * lda + kk + chunk * 8;
        const __half* Bp = B + (size_t)nBase * ldb + kk + chunk * 8;
        #pragma unroll
        for (int i = 0; i < 2; i++) {
            const int row = rbase + i * 64;
            const uint32_t so = SWZ64((uint32_t)(row * 64 + chunk * 16));
            cp16(bb + so,          Ap + (size_t)row * lda);          // Ah
            cp16(bb + OPTILE + so, Ap + kaLo + (size_t)row * lda);   // Al
            cp16(bb + 2 * OPTILE + so, Bp + (size_t)row * ldb);      // Bh
            if (NPASS == 3)
                cp16(bb + 3 * OPTILE + so, Bp + kbLo + (size_t)row * ldb); // Bl
        }
        cp_commit();
    };

    float acc[2][8][4];
    #pragma unroll
    for (int i = 0; i < 2; i++)
        #pragma unroll
        for (int j = 0; j < 8; j++)
            #pragma unroll
            for (int l = 0; l < 4; l++) acc[i][j][l] = 0.f;

    const int g = lane >> 2, tq = lane & 3;
    const int wm = (wid >> 1) * 32, wn = (wid & 1) * 64;
    const int rowSel = lane & 15;
    const uint32_t colB = (uint32_t)((lane >> 4) * 16);  // byte offset in row

    issue(0, 0);
    issue(1, 1);

    for (int t = 0; t < KT; t++) {
        const int slot = t % 3;
        cp_wait<1>();        // stage t resident (<=1 younger group pending)
        __syncthreads();     // all warps done with stage t-1 -> slot t+2 free
        if (t + 2 < KT) issue(t + 2, (t + 2) % 3);

        const uint32_t bb = base + slot * STAGE;
        #pragma unroll
        for (int ks = 0; ks < 2; ks++) {
            const uint32_t kbyte = (uint32_t)(ks * 32) + colB;

            uint32_t ah[2][4], al[2][4];
            #pragma unroll
            for (int mf = 0; mf < 2; mf++) {
                const uint32_t ro = (uint32_t)((wm + mf * 16 + rowSel) * 64);
                const uint32_t ad = bb + SWZ64(ro + kbyte);
                ldmx4(ah[mf], ad);
                ldmx4(al[mf], ad + OPTILE);
            }

            // consume B in two nf-halves to keep live registers low
            #pragma unroll
            for (int nh = 0; nh < 2; nh++) {
                uint32_t bh[4][2], bl[4][2];
                #pragma unroll
                for (int nb = 0; nb < 2; nb++) {
                    const uint32_t ro = (uint32_t)((wn + nh * 32 + nb * 16 + rowSel) * 64);
                    const uint32_t ad = bb + 2 * OPTILE + SWZ64(ro + kbyte);
                    uint32_t r[4];
                    ldmx4(r, ad);
                    bh[nb * 2][0] = r[0]; bh[nb * 2][1] = r[2];
                    bh[nb * 2 + 1][0] = r[1]; bh[nb * 2 + 1][1] = r[3];
                    if (NPASS == 3) {
                        uint32_t s[4];
                        ldmx4(s, ad + OPTILE);
                        bl[nb * 2][0] = s[0]; bl[nb * 2][1] = s[2];
                        bl[nb * 2 + 1][0] = s[1]; bl[nb * 2 + 1][1] = s[3];
                    }
                }
                #pragma unroll
                for (int mf = 0; mf < 2; mf++)
                    #pragma unroll
                    for (int nf = 0; nf < 4; nf++) {
                        float* a4 = acc[mf][nh * 4 + nf];
                        mma_f16(a4, ah[mf], bh[nf]);
                        mma_f16(a4, al[mf], bh[nf]);
                        if (NPASS == 3) mma_f16(a4, ah[mf], bl[nf]);
                    }
            }
        }
    }

    // epilogue: direct float2 stores; each STG fills complete 32B sectors.
    const bool hasB = (bias != nullptr);
    #pragma unroll
    for (int mf = 0; mf < 2; mf++) {
        const int row = mBase + wm + mf * 16 + g;
        #pragma unroll
        for (int nf = 0; nf < 8; nf++) {
            const int col = nBase + wn + nf * 8 + 2 * tq;
            const float b0 = hasB ? bias[col] : 0.f;
            const float b1 = hasB ? bias[col + 1] : 0.f;
            *(float2*)&C[(size_t)row * ldc + col] =
                make_float2(acc[mf][nf][0] + b0, acc[mf][nf][1] + b1);
            *(float2*)&C[(size_t)(row + 8) * ldc + col] =
                make_float2(acc[mf][nf][2] + b0, acc[mf][nf][3] + b1);
        }
    }
}

// ---------------------------------------------------------------------------
// Converters
// ---------------------------------------------------------------------------
__global__ __launch_bounds__(256)
void act_split_h(const float* __restrict__ X, __half* __restrict__ Y)
{
    const int idx = blockIdx.x * 256 + threadIdx.x;  // one float4 of a 512-col row
    const int row = idx >> 7, c4 = idx & 127;
    const float4 v = ((const float4*)X)[idx];
    float f[4] = { v.x, v.y, v.z, v.w };
    __half h[4], l[4];
    #pragma unroll
    for (int i = 0; i < 4; i++) {
        h[i] = __float2half_rn(f[i]);
        l[i] = __float2half_rn(f[i] - __half2float(h[i]));
    }
    const size_t o = (size_t)row * 1024 + c4 * 4;
    __half2* ph = (__half2*)(Y + o);
    ph[0] = __halves2half2(h[0], h[1]);
    ph[1] = __halves2half2(h[2], h[3]);
    __half2* pl = (__half2*)(Y + o + DMODEL);
    pl[0] = __halves2half2(l[0], l[1]);
    pl[1] = __halves2half2(l[2], l[3]);
}

// Batched transpose+split for Wq/Wk/Wv (blockIdx.z selects tensor).
__global__ __launch_bounds__(256)
void wtrans_split_qkv(const float* __restrict__ W0, __half* __restrict__ Y0,
                      const float* __restrict__ W1, __half* __restrict__ Y1,
                      const float* __restrict__ W2, __half* __restrict__ Y2)
{
    const float* W = (blockIdx.z == 0) ? W0 : (blockIdx.z == 1) ? W1 : W2;
    __half*      Y = (blockIdx.z == 0) ? Y0 : (blockIdx.z == 1) ? Y1 : Y2;
    const int Kin = DMODEL, Nin = DHID, ldo = 2 * DMODEL;

    __shared__ float t[32][33];
    const int n  = blockIdx.x * 32 + threadIdx.x;
    const int k0 = blockIdx.y * 32;
    #pragma unroll
    for (int i = 0; i < 4; i++)
        t[threadIdx.y + i * 8][threadIdx.x] = W[(size_t)(k0 + threadIdx.y + i * 8) * Nin + n];
    __syncthreads();
    const int kc = k0 + threadIdx.x;
    #pragma unroll
    for (int i = 0; i < 4; i++) {
        const int nr = blockIdx.x * 32 + threadIdx.y + i * 8;
        const float v = t[threadIdx.x][threadIdx.y + i * 8];
        const __half hi = __float2half_rn(v);
        const __half lo = __float2half_rn(v - __half2float(hi));
        Y[(size_t)nr * ldo + kc]       = hi;
        Y[(size_t)nr * ldo + Kin + kc] = lo;
    }
}

__global__ __launch_bounds__(256)
void wtrans_split_h(const float* __restrict__ W, __half* __restrict__ Y,
                    int Kin, int Nin, int ldo)
{
    __shared__ float t[32][33];
    const int n  = blockIdx.x * 32 + threadIdx.x;
    const int k0 = blockIdx.y * 32;
    #pragma unroll
    for (int i = 0; i < 4; i++)
        t[threadIdx.y + i * 8][threadIdx.x] = W[(size_t)(k0 + threadIdx.y + i * 8) * Nin + n];
    __syncthreads();
    const int kc = k0 + threadIdx.x;
    #pragma unroll
    for (int i = 0; i < 4; i++) {
        const int nr = blockIdx.x * 32 + threadIdx.y + i * 8;
        const float v = t[threadIdx.x][threadIdx.y + i * 8];
        const __half hi = __float2half_rn(v);
        const __half lo = __float2half_rn(v - __half2float(hi));
        Y[(size_t)nr * ldo + kc]       = hi;
        Y[(size_t)nr * ldo + Kin + kc] = lo;
    }
}

// ---------------------------------------------------------------------------
// Per-token attention (8x8 over heads); writes AO as split fp16 [hi|lo].
// ---------------------------------------------------------------------------
__global__ __launch_bounds__(128)
void attn_kernel()
{
    const int n = blockIdx.x;
    const int tid = threadIdx.x;
    const size_t base = (size_t)n * DHID;
    const size_t b2 = (size_t)n * (2 * DHID);

    __shared__ float red[4][64];
    __shared__ float Sf[64];
    __shared__ float P[64];

    float q[8][4], k[8][4];
    #pragma unroll
    for (int h = 0; h < 8; h++)
        #pragma unroll
        for (int j = 0; j < 4; j++) {
            const int d = tid + j * 128;
            q[h][j] = g_Q[base + h * DMODEL + d];
            k[h][j] = g_K[base + h * DMODEL + d];
        }

    float s[64];
    #pragma unroll
    for (int h = 0; h < 8; h++)
        #pragma unroll
        for (int gg = 0; gg < 8; gg++) {
            float a = 0.f;
            #pragma unroll
            for (int j = 0; j < 4; j++) a += q[h][j] * k[gg][j];
            s[h * 8 + gg] = a;
        }

    const int lane = tid & 31, w = tid >> 5;
    #pragma unroll
    for (int i = 0; i < 64; i++) {
        float v = s[i];
        v += __shfl_down_sync(0xffffffffu, v, 16);
        v += __shfl_down_sync(0xffffffffu, v, 8);
        v += __shfl_down_sync(0xffffffffu, v, 4);
        v += __shfl_down_sync(0xffffffffu, v, 2);
        v += __shfl_down_sync(0xffffffffu, v, 1);
        if (lane == 0) red[w][i] = v;
    }
    __syncthreads();
    if (tid < 64) Sf[tid] = red[0][tid] + red[1][tid] + red[2][tid] + red[3][tid];
    __syncthreads();
    if (tid < 8) {
        float m = -1e30f;
        #pragma unroll
        for (int gg = 0; gg < 8; gg++) m = fmaxf(m, Sf[tid * 8 + gg]);
        float e[8], sum = 0.f;
        #pragma unroll
        for (int gg = 0; gg < 8; gg++) { e[gg] = expf(Sf[tid * 8 + gg] - m); sum += e[gg]; }
        const float inv = 1.f / sum;
        #pragma unroll
        for (int gg = 0; gg < 8; gg++) P[tid * 8 + gg] = e[gg] * inv;
    }
    __syncthreads();

    float vv[8][4];
    #pragma unroll
    for (int h = 0; h < 8; h++)
        #pragma unroll
        for (int j = 0; j < 4; j++)
            vv[h][j] = g_V[base + h * DMODEL + tid + j * 128];

    #pragma unroll
    for (int h = 0; h < 8; h++) {
        #pragma unroll
        for (int j = 0; j < 4; j++) {
            float o = 0.f;
            #pragma unroll
            for (int gg = 0; gg < 8; gg++) o += P[h * 8 + gg] * vv[gg][j];
            const int d = h * DMODEL + tid + j * 128;
            const __half hi = __float2half_rn(o);
            const __half lo = __float2half_rn(o - __half2float(hi));
            g_AOs[b2 + d]        = hi;
            g_AOs[b2 + DHID + d] = lo;
        }
    }
}

// ---------------------------------------------------------------------------
// launch
// ---------------------------------------------------------------------------
extern "C" void kernel_launch(void* const* d_in, const int* in_sizes, int n_in,
                              void* d_out, int out_size)
{
    const float* queries = (const float*)d_in[0];
    const float* keys    = (const float*)d_in[1];
    const float* values  = (const float*)d_in[2];
    const float* Wq      = (const float*)d_in[3];
    const float* Wk      = (const float*)d_in[4];
    const float* Wv      = (const float*)d_in[5];
    const float* Wo      = (const float*)d_in[6];
    const float* bo      = (const float*)d_in[7];
    float* out = (float*)d_out;

    float *Qp, *Kp, *Vp;
    __half *Xq, *Xk, *Xv, *Wqs, *Wks, *Wvs, *Wos, *AOs;
    cudaGetSymbolAddress((void**)&Qp,  g_Q);
    cudaGetSymbolAddress((void**)&Kp,  g_K);
    cudaGetSymbolAddress((void**)&Vp,  g_V);
    cudaGetSymbolAddress((void**)&Xq,  g_Xq);
    cudaGetSymbolAddress((void**)&Xk,  g_Xk);
    cudaGetSymbolAddress((void**)&Xv,  g_Xv);
    cudaGetSymbolAddress((void**)&Wqs, g_Wqs);
    cudaGetSymbolAddress((void**)&Wks, g_Wks);
    cudaGetSymbolAddress((void**)&Wvs, g_Wvs);
    cudaGetSymbolAddress((void**)&Wos, g_Wos);
    cudaGetSymbolAddress((void**)&AOs, g_AOs);

    const int SM3 = 1024 + NSTAGE * 4 * OPTILE;  // 97.3 KB -> 2 CTAs/SM
    const int SM2 = 1024 + NSTAGE * 3 * OPTILE;  // 73.0 KB -> 2 CTAs/SM
    cudaFuncSetAttribute(gemm_split_hmma<3>,
                         cudaFuncAttributeMaxDynamicSharedMemorySize, SM3);
    cudaFuncSetAttribute(gemm_split_hmma<2>,
                         cudaFuncAttributeMaxDynamicSharedMemorySize, SM2);

    // 1) split converts
    act_split_h<<<16384, 256>>>(queries, Xq);
    act_split_h<<<16384, 256>>>(keys,    Xk);
    act_split_h<<<16384, 256>>>(values,  Xv);
    wtrans_split_qkv<<<dim3(DHID / 32, DMODEL / 32, 3), dim3(32, 8)>>>(
        Wq, Wqs, Wk, Wks, Wv, Wvs);
    wtrans_split_h<<<dim3(DMODEL / 32, DHID / 32), dim3(32, 8)>>>(
        Wo, Wos, DHID, DMODEL, 2 * DHID);

    // 2) projections
    dim3 gProj(DHID / 128, NTOK / 128);   // (32, 256)
    gemm_split_hmma<3><<<gProj, 256, SM3>>>(Xq, 2 * DMODEL, DMODEL, Wqs, 2 * DMODEL, DMODEL,
                                            Qp, DHID, nullptr, DMODEL / 32);
    gemm_split_hmma<3><<<gProj, 256, SM3>>>(Xk, 2 * DMODEL, DMODEL, Wks, 2 * DMODEL, DMODEL,
                                            Kp, DHID, nullptr, DMODEL / 32);
    gemm_split_hmma<2><<<gProj, 256, SM2>>>(Xv, 2 * DMODEL, DMODEL, Wvs, 2 * DMODEL, DMODEL,
                                            Vp, DHID, nullptr, DMODEL / 32);

    // 3) per-token attention -> split fp16 AO
    attn_kernel<<<NTOK, 128>>>();

    // 4) output projection + bias
    dim3 gOut(DMODEL / 128, NTOK / 128);  // (4, 256)
    gemm_split_hmma<2><<<gOut, 256, SM2>>>(AOs, 2 * DHID, DHID, Wos, 2 * DHID, DHID,
                                           out, DMODEL, bo, DHID / 32);
}

// round 14
// speedup vs baseline: 1.3590x; 1.2311x over previous
#include <cuda_runtime.h>
#include <cuda_fp16.h>
#include <cstdint>

// ============================================================================
// CrossAttention via fp16-split mma.sync GEMMs (sm_103-safe: no arch-'a' ops).
//   out = softmax((Xq Wq)(Xk Wk)^T over heads) (Xv Wv) Wo + bo
// N=32768, D=512, H=8.
//
// GEMM precision (pass count set by error budget; threshold rel_err < 1e-3):
//   NPASS=3 (Q,K): Ah*Bh + Al*Bh + Ah*Bl  (~2^-22; softmax amplifies ~5x)
//   NPASS=1 (V,O): Ah*Bh                  (~3e-4 each, unamplified)
// Issued tensor work: 8 pass-equivalents (was 10 in R12).
// ============================================================================

#define NTOK 32768
#define DMODEL 512
#define DHID 4096

// ---------------- scratch (device globals; allocation-free) -----------------
__device__ float g_Q[(size_t)NTOK * DHID];
__device__ float g_K[(size_t)NTOK * DHID];
__device__ float g_V[(size_t)NTOK * DHID];
__device__ __half g_AOh[(size_t)NTOK * DHID];         // [32768][4096] fp16 (hi only)
__device__ __half g_Xq[(size_t)NTOK * 2 * DMODEL];    // [32768][1024] hi|lo
__device__ __half g_Xk[(size_t)NTOK * 2 * DMODEL];
__device__ __half g_Xv[(size_t)NTOK * 2 * DMODEL];
__device__ __half g_Wqs[(size_t)DHID * 2 * DMODEL];   // [4096][1024] K-major hi|lo
__device__ __half g_Wks[(size_t)DHID * 2 * DMODEL];
__device__ __half g_Wvs[(size_t)DHID * 2 * DMODEL];
__device__ __half g_Wos[(size_t)DMODEL * 2 * DHID];   // [512][8192]  K-major hi|lo

// ---------------------------- PTX helpers -----------------------------------
__device__ __forceinline__ uint32_t smem_u32(const void* p) {
    uint32_t a;
    asm("{ .reg .u64 t; cvta.to.shared.u64 t, %1; cvt.u32.u64 %0, t; }" : "=r"(a) : "l"(p));
    return a;
}
// SW64 swizzle: 64-byte rows, atom = 8 rows x 64B. Conflict-free for both
// cp.async 16B stores and ldmatrix 8x16B row gathers.
#define SWZ64(x) ((x) ^ (((x) >> 3) & 0x30))

__device__ __forceinline__ void cp16(uint32_t dst, const void* src) {
    asm volatile("cp.async.cg.shared.global [%0], [%1], 16;\n" :: "r"(dst), "l"(src));
}
__device__ __forceinline__ void cp_commit() { asm volatile("cp.async.commit_group;\n"); }
template<int Ng> __device__ __forceinline__ void cp_wait() {
    asm volatile("cp.async.wait_group %0;\n" :: "n"(Ng));
}

__device__ __forceinline__ void ldmx4(uint32_t* r, uint32_t addr) {
    asm volatile("ldmatrix.sync.aligned.m8n8.x4.shared.b16 {%0,%1,%2,%3}, [%4];"
                 : "=r"(r[0]), "=r"(r[1]), "=r"(r[2]), "=r"(r[3]) : "r"(addr));
}

__device__ __forceinline__ void mma_f16(float* d, const uint32_t* a, const uint32_t* b) {
    asm volatile(
        "mma.sync.aligned.m16n8k16.row.col.f32.f16.f16.f32 "
        "{%0,%1,%2,%3}, {%4,%5,%6,%7}, {%8,%9}, {%0,%1,%2,%3};\n"
        : "+f"(d[0]), "+f"(d[1]), "+f"(d[2]), "+f"(d[3])
        : "r"(a[0]), "r"(a[1]), "r"(a[2]), "r"(a[3]), "r"(b[0]), "r"(b[1]));
}

// ---------------------------------------------------------------------------
// GEMM: C[M,N] = A @ B^T, A:[rows][lda] fp16 (hi, lo at +kaLo if NPASS>=2),
// B:[N rows][ldb] K-major fp16 (hi, lo at +kbLo if NPASS==3).
// CTA tile 128x128, BK=32 (64B SW64 rows), 3-stage cp.async, 256 threads =
// 8 warps (4x2), warp tile 32x64. 2 CTAs/SM.
// ---------------------------------------------------------------------------
constexpr int OPTILE = 128 * 64;   // 8 KB: one 128x32 fp16 operand tile
constexpr int NSTAGE = 3;

template<int NPASS>
__global__ __launch_bounds__(256, 2)
void gemm_split_hmma(const __half* __restrict__ A, int lda, int kaLo,
                     const __half* __restrict__ B, int ldb, int kbLo,
                     float* __restrict__ C, int ldc,
                     const float* __restrict__ bias, int KT)
{
    constexpr int NT = (NPASS == 3) ? 4 : (NPASS == 2) ? 3 : 2;  // Ah[,Al],Bh[,Bl]
    constexpr int AL_OFF = OPTILE;                        // valid if NPASS>=2
    constexpr int BH_OFF = (NPASS >= 2 ? 2 : 1) * OPTILE;
    constexpr int BL_OFF = 3 * OPTILE;                    // valid if NPASS==3
    constexpr int STAGE = NT * OPTILE;
    extern __shared__ char smraw[];
    const uint32_t base = (smem_u32(smraw) + 1023u) & ~1023u;

    const int tid = threadIdx.x, wid = tid >> 5, lane = tid & 31;
    const int mBase = blockIdx.y * 128, nBase = blockIdx.x * 128;

    const int chunk = tid & 3;       // 16B chunk within a 64B row
    const int rbase = tid >> 2;      // 0..63

    auto issue = [&](int t, int slot) {
        const int kk = t * 32;
        const uint32_t bb = base + slot * STAGE;
        const __half* Ap = A + (size_t)mBase * lda + kk + chunk * 8;
        const __half* Bp = B + (size_t)nBase * ldb + kk + chunk * 8;
        #pragma unroll
        for (int i = 0; i < 2; i++) {
            const int row = rbase + i * 64;
            const uint32_t so = SWZ64((uint32_t)(row * 64 + chunk * 16));
            cp16(bb + so, Ap + (size_t)row * lda);                          // Ah
            if (NPASS >= 2)
                cp16(bb + AL_OFF + so, Ap + kaLo + (size_t)row * lda);      // Al
            cp16(bb + BH_OFF + so, Bp + (size_t)row * ldb);                 // Bh
            if (NPASS == 3)
                cp16(bb + BL_OFF + so, Bp + kbLo + (size_t)row * ldb);      // Bl
        }
        cp_commit();
    };

    float acc[2][8][4];
    #pragma unroll
    for (int i = 0; i < 2; i++)
        #pragma unroll
        for (int j = 0; j < 8; j++)
            #pragma unroll
            for (int l = 0; l < 4; l++) acc[i][j][l] = 0.f;

    const int g = lane >> 2, tq = lane & 3;
    const int wm = (wid >> 1) * 32, wn = (wid & 1) * 64;
    const int rowSel = lane & 15;
    const uint32_t colB = (uint32_t)((lane >> 4) * 16);  // byte offset in row

    issue(0, 0);
    issue(1, 1);

    for (int t = 0; t < KT; t++) {
        const int slot = t % 3;
        cp_wait<1>();        // stage t resident (<=1 younger group pending)
        __syncthreads();     // all warps done with stage t-1 -> slot t+2 free
        if (t + 2 < KT) issue(t + 2, (t + 2) % 3);

        const uint32_t bb = base + slot * STAGE;
        #pragma unroll
        for (int ks = 0; ks < 2; ks++) {
            const uint32_t kbyte = (uint32_t)(ks * 32) + colB;

            uint32_t ah[2][4], al[2][4];
            #pragma unroll
            for (int mf = 0; mf < 2; mf++) {
                const uint32_t ro = (uint32_t)((wm + mf * 16 + rowSel) * 64);
                const uint32_t ad = bb + SWZ64(ro + kbyte);
                ldmx4(ah[mf], ad);
                if (NPASS >= 2) ldmx4(al[mf], ad + AL_OFF);
            }

            // consume B in two nf-halves to keep live registers low
            #pragma unroll
            for (int nh = 0; nh < 2; nh++) {
                uint32_t bh[4][2], bl[4][2];
                #pragma unroll
                for (int nb = 0; nb < 2; nb++) {
                    const uint32_t ro = (uint32_t)((wn + nh * 32 + nb * 16 + rowSel) * 64);
                    const uint32_t ad = bb + BH_OFF + SWZ64(ro + kbyte);
                    uint32_t r[4];
                    ldmx4(r, ad);
                    bh[nb * 2][0] = r[0]; bh[nb * 2][1] = r[2];
                    bh[nb * 2 + 1][0] = r[1]; bh[nb * 2 + 1][1] = r[3];
                    if (NPASS == 3) {
                        uint32_t s[4];
                        ldmx4(s, ad + (BL_OFF - BH_OFF));
                        bl[nb * 2][0] = s[0]; bl[nb * 2][1] = s[2];
                        bl[nb * 2 + 1][0] = s[1]; bl[nb * 2 + 1][1] = s[3];
                    }
                }
                #pragma unroll
                for (int mf = 0; mf < 2; mf++)
                    #pragma unroll
                    for (int nf = 0; nf < 4; nf++) {
                        float* a4 = acc[mf][nh * 4 + nf];
                        mma_f16(a4, ah[mf], bh[nf]);
                        if (NPASS >= 2) mma_f16(a4, al[mf], bh[nf]);
                        if (NPASS == 3) mma_f16(a4, ah[mf], bl[nf]);
                    }
            }
        }
    }

    // epilogue: direct float2 stores; each STG fills complete 32B sectors.
    const bool hasB = (bias != nullptr);
    #pragma unroll
    for (int mf = 0; mf < 2; mf++) {
        const int row = mBase + wm + mf * 16 + g;
        #pragma unroll
        for (int nf = 0; nf < 8; nf++) {
            const int col = nBase + wn + nf * 8 + 2 * tq;
            const float b0 = hasB ? bias[col] : 0.f;
            const float b1 = hasB ? bias[col + 1] : 0.f;
            *(float2*)&C[(size_t)row * ldc + col] =
                make_float2(acc[mf][nf][0] + b0, acc[mf][nf][1] + b1);
            *(float2*)&C[(size_t)(row + 8) * ldc + col] =
                make_float2(acc[mf][nf][2] + b0, acc[mf][nf][3] + b1);
        }
    }
}

// ---------------------------------------------------------------------------
// Converters
// ---------------------------------------------------------------------------
__global__ __launch_bounds__(256)
void act_split_h(const float* __restrict__ X, __half* __restrict__ Y)
{
    const int idx = blockIdx.x * 256 + threadIdx.x;  // one float4 of a 512-col row
    const int row = idx >> 7, c4 = idx & 127;
    const float4 v = ((const float4*)X)[idx];
    float f[4] = { v.x, v.y, v.z, v.w };
    __half h[4], l[4];
    #pragma unroll
    for (int i = 0; i < 4; i++) {
        h[i] = __float2half_rn(f[i]);
        l[i] = __float2half_rn(f[i] - __half2float(h[i]));
    }
    const size_t o = (size_t)row * 1024 + c4 * 4;
    __half2* ph = (__half2*)(Y + o);
    ph[0] = __halves2half2(h[0], h[1]);
    ph[1] = __halves2half2(h[2], h[3]);
    __half2* pl = (__half2*)(Y + o + DMODEL);
    pl[0] = __halves2half2(l[0], l[1]);
    pl[1] = __halves2half2(l[2], l[3]);
}

// Batched transpose+split for Wq/Wk/Wv (blockIdx.z selects tensor).
__global__ __launch_bounds__(256)
void wtrans_split_qkv(const float* __restrict__ W0, __half* __restrict__ Y0,
                      const float* __restrict__ W1, __half* __restrict__ Y1,
                      const float* __restrict__ W2, __half* __restrict__ Y2)
{
    const float* W = (blockIdx.z == 0) ? W0 : (blockIdx.z == 1) ? W1 : W2;
    __half*      Y = (blockIdx.z == 0) ? Y0 : (blockIdx.z == 1) ? Y1 : Y2;
    const int Kin = DMODEL, Nin = DHID, ldo = 2 * DMODEL;

    __shared__ float t[32][33];
    const int n  = blockIdx.x * 32 + threadIdx.x;
    const int k0 = blockIdx.y * 32;
    #pragma unroll
    for (int i = 0; i < 4; i++)
        t[threadIdx.y + i * 8][threadIdx.x] = W[(size_t)(k0 + threadIdx.y + i * 8) * Nin + n];
    __syncthreads();
    const int kc = k0 + threadIdx.x;
    #pragma unroll
    for (int i = 0; i < 4; i++) {
        const int nr = blockIdx.x * 32 + threadIdx.y + i * 8;
        const float v = t[threadIdx.x][threadIdx.y + i * 8];
        const __half hi = __float2half_rn(v);
        const __half lo = __float2half_rn(v - __half2float(hi));
        Y[(size_t)nr * ldo + kc]       = hi;
        Y[(size_t)nr * ldo + Kin + kc] = lo;
    }
}

__global__ __launch_bounds__(256)
void wtrans_split_h(const float* __restrict__ W, __half* __restrict__ Y,
                    int Kin, int Nin, int ldo)
{
    __shared__ float t[32][33];
    const int n  = blockIdx.x * 32 + threadIdx.x;
    const int k0 = blockIdx.y * 32;
    #pragma unroll
    for (int i = 0; i < 4; i++)
        t[threadIdx.y + i * 8][threadIdx.x] = W[(size_t)(k0 + threadIdx.y + i * 8) * Nin + n];
    __syncthreads();
    const int kc = k0 + threadIdx.x;
    #pragma unroll
    for (int i = 0; i < 4; i++) {
        const int nr = blockIdx.x * 32 + threadIdx.y + i * 8;
        const float v = t[threadIdx.x][threadIdx.y + i * 8];
        const __half hi = __float2half_rn(v);
        const __half lo = __float2half_rn(v - __half2float(hi));
        Y[(size_t)nr * ldo + kc]       = hi;
        Y[(size_t)nr * ldo + Kin + kc] = lo;
    }
}

// ---------------------------------------------------------------------------
// Per-token attention (8x8 over heads); writes AO as fp16 (hi only — this IS
// the Ah operand of the 1-pass output GEMM).
// ---------------------------------------------------------------------------
__global__ __launch_bounds__(128)
void attn_kernel()
{
    const int n = blockIdx.x;
    const int tid = threadIdx.x;
    const size_t base = (size_t)n * DHID;

    __shared__ float red[4][64];
    __shared__ float Sf[64];
    __shared__ float P[64];

    float q[8][4], k[8][4];
    #pragma unroll
    for (int h = 0; h < 8; h++)
        #pragma unroll
        for (int j = 0; j < 4; j++) {
            const int d = tid + j * 128;
            q[h][j] = g_Q[base + h * DMODEL + d];
            k[h][j] = g_K[base + h * DMODEL + d];
        }

    float s[64];
    #pragma unroll
    for (int h = 0; h < 8; h++)
        #pragma unroll
        for (int gg = 0; gg < 8; gg++) {
            float a = 0.f;
            #pragma unroll
            for (int j = 0; j < 4; j++) a += q[h][j] * k[gg][j];
            s[h * 8 + gg] = a;
        }

    const int lane = tid & 31, w = tid >> 5;
    #pragma unroll
    for (int i = 0; i < 64; i++) {
        float v = s[i];
        v += __shfl_down_sync(0xffffffffu, v, 16);
        v += __shfl_down_sync(0xffffffffu, v, 8);
        v += __shfl_down_sync(0xffffffffu, v, 4);
        v += __shfl_down_sync(0xffffffffu, v, 2);
        v += __shfl_down_sync(0xffffffffu, v, 1);
        if (lane == 0) red[w][i] = v;
    }
    __syncthreads();
    if (tid < 64) Sf[tid] = red[0][tid] + red[1][tid] + red[2][tid] + red[3][tid];
    __syncthreads();
    if (tid < 8) {
        float m = -1e30f;
        #pragma unroll
        for (int gg = 0; gg < 8; gg++) m = fmaxf(m, Sf[tid * 8 + gg]);
        float e[8], sum = 0.f;
        #pragma unroll
        for (int gg = 0; gg < 8; gg++) { e[gg] = expf(Sf[tid * 8 + gg] - m); sum += e[gg]; }
        const float inv = 1.f / sum;
        #pragma unroll
        for (int gg = 0; gg < 8; gg++) P[tid * 8 + gg] = e[gg] * inv;
    }
    __syncthreads();

    float vv[8][4];
    #pragma unroll
    for (int h = 0; h < 8; h++)
        #pragma unroll
        for (int j = 0; j < 4; j++)
            vv[h][j] = g_V[base + h * DMODEL + tid + j * 128];

    #pragma unroll
    for (int h = 0; h < 8; h++) {
        #pragma unroll
        for (int j = 0; j < 4; j++) {
            float o = 0.f;
            #pragma unroll
            for (int gg = 0; gg < 8; gg++) o += P[h * 8 + gg] * vv[gg][j];
            g_AOh[base + h * DMODEL + tid + j * 128] = __float2half_rn(o);
        }
    }
}

// ---------------------------------------------------------------------------
// launch
// ---------------------------------------------------------------------------
extern "C" void kernel_launch(void* const* d_in, const int* in_sizes, int n_in,
                              void* d_out, int out_size)
{
    const float* queries = (const float*)d_in[0];
    const float* keys    = (const float*)d_in[1];
    const float* values  = (const float*)d_in[2];
    const float* Wq      = (const float*)d_in[3];
    const float* Wk      = (const float*)d_in[4];
    const float* Wv      = (const float*)d_in[5];
    const float* Wo      = (const float*)d_in[6];
    const float* bo      = (const float*)d_in[7];
    float* out = (float*)d_out;

    float *Qp, *Kp, *Vp;
    __half *Xq, *Xk, *Xv, *Wqs, *Wks, *Wvs, *Wos, *AOh;
    cudaGetSymbolAddress((void**)&Qp,  g_Q);
    cudaGetSymbolAddress((void**)&Kp,  g_K);
    cudaGetSymbolAddress((void**)&Vp,  g_V);
    cudaGetSymbolAddress((void**)&Xq,  g_Xq);
    cudaGetSymbolAddress((void**)&Xk,  g_Xk);
    cudaGetSymbolAddress((void**)&Xv,  g_Xv);
    cudaGetSymbolAddress((void**)&Wqs, g_Wqs);
    cudaGetSymbolAddress((void**)&Wks, g_Wks);
    cudaGetSymbolAddress((void**)&Wvs, g_Wvs);
    cudaGetSymbolAddress((void**)&Wos, g_Wos);
    cudaGetSymbolAddress((void**)&AOh, g_AOh);

    const int SM3 = 1024 + NSTAGE * 4 * OPTILE;  // 97.3 KB -> 2 CTAs/SM
    const int SM1 = 1024 + NSTAGE * 2 * OPTILE;  // 49.2 KB -> 2 CTAs/SM
    cudaFuncSetAttribute(gemm_split_hmma<3>,
                         cudaFuncAttributeMaxDynamicSharedMemorySize, SM3);
    cudaFuncSetAttribute(gemm_split_hmma<1>,
                         cudaFuncAttributeMaxDynamicSharedMemorySize, SM1);

    // 1) split converts
    act_split_h<<<16384, 256>>>(queries, Xq);
    act_split_h<<<16384, 256>>>(keys,    Xk);
    act_split_h<<<16384, 256>>>(values,  Xv);
    wtrans_split_qkv<<<dim3(DHID / 32, DMODEL / 32, 3), dim3(32, 8)>>>(
        Wq, Wqs, Wk, Wks, Wv, Wvs);
    wtrans_split_h<<<dim3(DMODEL / 32, DHID / 32), dim3(32, 8)>>>(
        Wo, Wos, DHID, DMODEL, 2 * DHID);

    // 2) projections: Q,K 3-pass; V 1-pass
    dim3 gProj(DHID / 128, NTOK / 128);   // (32, 256)
    gemm_split_hmma<3><<<gProj, 256, SM3>>>(Xq, 2 * DMODEL, DMODEL, Wqs, 2 * DMODEL, DMODEL,
                                            Qp, DHID, nullptr, DMODEL / 32);
    gemm_split_hmma<3><<<gProj, 256, SM3>>>(Xk, 2 * DMODEL, DMODEL, Wks, 2 * DMODEL, DMODEL,
                                            Kp, DHID, nullptr, DMODEL / 32);
    gemm_split_hmma<1><<<gProj, 256, SM1>>>(Xv, 2 * DMODEL, 0, Wvs, 2 * DMODEL, 0,
                                            Vp, DHID, nullptr, DMODEL / 32);

    // 3) per-token attention -> fp16 AO (hi only)
    attn_kernel<<<NTOK, 128>>>();

    // 4) output projection + bias: 1-pass
    dim3 gOut(DMODEL / 128, NTOK / 128);  // (4, 256)
    gemm_split_hmma<1><<<gOut, 256, SM1>>>(AOh, DHID, 0, Wos, 2 * DHID, 0,
                                           out, DMODEL, bo, DHID / 32);
}

// round 15
// speedup vs baseline: 1.3615x; 1.0019x over previous
#include <cuda_runtime.h>
#include <cuda_fp16.h>
#include <cstdint>

// ============================================================================
// CrossAttention via fp16-split mma.sync GEMMs (sm_103-safe: no arch-'a' ops).
//   out = softmax((Xq Wq)(Xk Wk)^T over heads) (Xv Wv) Wo + bo
// N=32768, D=512, H=8.
//
// GEMM precision (pass count set by error budget; threshold rel_err < 1e-3):
//   NPASS=3 (Q,K): Ah*Bh + Al*Bh + Ah*Bl  (~2^-22; softmax amplifies ~5x)
//   NPASS=1 (V,O): Ah*Bh                  (~3e-4 each, unamplified)
//
// R14: V flows fp16 end-to-end (HOUT epilogue), Wo stored hi-only packed,
//      act_split fused to one launch. Pure traffic reduction; GEMM passes
//      unchanged (8 pass-equivalents, floor for this scheme).
// ============================================================================

#define NTOK 32768
#define DMODEL 512
#define DHID 4096

// ---------------- scratch (device globals; allocation-free) -----------------
__device__ float g_Q[(size_t)NTOK * DHID];
__device__ float g_K[(size_t)NTOK * DHID];
__device__ __half g_Vh[(size_t)NTOK * DHID];          // V projection, fp16
__device__ __half g_AOh[(size_t)NTOK * DHID];         // attn output, fp16
__device__ __half g_Xq[(size_t)NTOK * 2 * DMODEL];    // [32768][1024] hi|lo
__device__ __half g_Xk[(size_t)NTOK * 2 * DMODEL];
__device__ __half g_Xv[(size_t)NTOK * 2 * DMODEL];
__device__ __half g_Wqs[(size_t)DHID * 2 * DMODEL];   // [4096][1024] K-major hi|lo
__device__ __half g_Wks[(size_t)DHID * 2 * DMODEL];
__device__ __half g_Wvs[(size_t)DHID * 2 * DMODEL];
__device__ __half g_Woh[(size_t)DMODEL * DHID];       // [512][4096] K-major hi only

// ---------------------------- PTX helpers -----------------------------------
__device__ __forceinline__ uint32_t smem_u32(const void* p) {
    uint32_t a;
    asm("{ .reg .u64 t; cvta.to.shared.u64 t, %1; cvt.u32.u64 %0, t; }" : "=r"(a) : "l"(p));
    return a;
}
// SW64 swizzle: 64-byte rows, atom = 8 rows x 64B. Conflict-free for both
// cp.async 16B stores and ldmatrix 8x16B row gathers.
#define SWZ64(x) ((x) ^ (((x) >> 3) & 0x30))

__device__ __forceinline__ void cp16(uint32_t dst, const void* src) {
    asm volatile("cp.async.cg.shared.global [%0], [%1], 16;\n" :: "r"(dst), "l"(src));
}
__device__ __forceinline__ void cp_commit() { asm volatile("cp.async.commit_group;\n"); }
template<int Ng> __device__ __forceinline__ void cp_wait() {
    asm volatile("cp.async.wait_group %0;\n" :: "n"(Ng));
}

__device__ __forceinline__ void ldmx4(uint32_t* r, uint32_t addr) {
    asm volatile("ldmatrix.sync.aligned.m8n8.x4.shared.b16 {%0,%1,%2,%3}, [%4];"
                 : "=r"(r[0]), "=r"(r[1]), "=r"(r[2]), "=r"(r[3]) : "r"(addr));
}

__device__ __forceinline__ void mma_f16(float* d, const uint32_t* a, const uint32_t* b) {
    asm volatile(
        "mma.sync.aligned.m16n8k16.row.col.f32.f16.f16.f32 "
        "{%0,%1,%2,%3}, {%4,%5,%6,%7}, {%8,%9}, {%0,%1,%2,%3};\n"
        : "+f"(d[0]), "+f"(d[1]), "+f"(d[2]), "+f"(d[3])
        : "r"(a[0]), "r"(a[1]), "r"(a[2]), "r"(a[3]), "r"(b[0]), "r"(b[1]));
}

// ---------------------------------------------------------------------------
// GEMM: C[M,N] = A @ B^T, A:[rows][lda] fp16 (hi, lo at +kaLo if NPASS>=2),
// B:[N rows][ldb] K-major fp16 (hi, lo at +kbLo if NPASS==3).
// CTA tile 128x128, BK=32 (64B SW64 rows), 3-stage cp.async, 256 threads =
// 8 warps (4x2), warp tile 32x64. 2 CTAs/SM. HOUT: write C as fp16.
// ---------------------------------------------------------------------------
constexpr int OPTILE = 128 * 64;   // 8 KB: one 128x32 fp16 operand tile
constexpr int NSTAGE = 3;

template<int NPASS, bool HOUT>
__global__ __launch_bounds__(256, 2)
void gemm_split_hmma(const __half* __restrict__ A, int lda, int kaLo,
                     const __half* __restrict__ B, int ldb, int kbLo,
                     void* __restrict__ Cout, int ldc,
                     const float* __restrict__ bias, int KT)
{
    constexpr int NT = (NPASS == 3) ? 4 : (NPASS == 2) ? 3 : 2;  // Ah[,Al],Bh[,Bl]
    constexpr int AL_OFF = OPTILE;                        // valid if NPASS>=2
    constexpr int BH_OFF = (NPASS >= 2 ? 2 : 1) * OPTILE;
    constexpr int BL_OFF = 3 * OPTILE;                    // valid if NPASS==3
    constexpr int STAGE = NT * OPTILE;
    extern __shared__ char smraw[];
    const uint32_t base = (smem_u32(smraw) + 1023u) & ~1023u;

    const int tid = threadIdx.x, wid = tid >> 5, lane = tid & 31;
    const int mBase = blockIdx.y * 128, nBase = blockIdx.x * 128;

    const int chunk = tid & 3;       // 16B chunk within a 64B row
    const int rbase = tid >> 2;      // 0..63

    auto issue = [&](int t, int slot) {
        const int kk = t * 32;
        const uint32_t bb = base + slot * STAGE;
        const __half* Ap = A + (size_t)mBase * lda + kk + chunk * 8;
        const __half* Bp = B + (size_t)nBase * ldb + kk + chunk * 8;
        #pragma unroll
        for (int i = 0; i < 2; i++) {
            const int row = rbase + i * 64;
            const uint32_t so = SWZ64((uint32_t)(row * 64 + chunk * 16));
            cp16(bb + so, Ap + (size_t)row * lda);                          // Ah
            if (NPASS >= 2)
                cp16(bb + AL_OFF + so, Ap + kaLo + (size_t)row * lda);      // Al
            cp16(bb + BH_OFF + so, Bp + (size_t)row * ldb);                 // Bh
            if (NPASS == 3)
                cp16(bb + BL_OFF + so, Bp + kbLo + (size_t)row * ldb);      // Bl
        }
        cp_commit();
    };

    float acc[2][8][4];
    #pragma unroll
    for (int i = 0; i < 2; i++)
        #pragma unroll
        for (int j = 0; j < 8; j++)
            #pragma unroll
            for (int l = 0; l < 4; l++) acc[i][j][l] = 0.f;

    const int g = lane >> 2, tq = lane & 3;
    const int wm = (wid >> 1) * 32, wn = (wid & 1) * 64;
    const int rowSel = lane & 15;
    const uint32_t colB = (uint32_t)((lane >> 4) * 16);  // byte offset in row

    issue(0, 0);
    issue(1, 1);

    for (int t = 0; t < KT; t++) {
        const int slot = t % 3;
        cp_wait<1>();        // stage t resident (<=1 younger group pending)
        __syncthreads();     // all warps done with stage t-1 -> slot t+2 free
        if (t + 2 < KT) issue(t + 2, (t + 2) % 3);

        const uint32_t bb = base + slot * STAGE;
        #pragma unroll
        for (int ks = 0; ks < 2; ks++) {
            const uint32_t kbyte = (uint32_t)(ks * 32) + colB;

            uint32_t ah[2][4], al[2][4];
            #pragma unroll
            for (int mf = 0; mf < 2; mf++) {
                const uint32_t ro = (uint32_t)((wm + mf * 16 + rowSel) * 64);
                const uint32_t ad = bb + SWZ64(ro + kbyte);
                ldmx4(ah[mf], ad);
                if (NPASS >= 2) ldmx4(al[mf], ad + AL_OFF);
            }

            // consume B in two nf-halves to keep live registers low
            #pragma unroll
            for (int nh = 0; nh < 2; nh++) {
                uint32_t bh[4][2], bl[4][2];
                #pragma unroll
                for (int nb = 0; nb < 2; nb++) {
                    const uint32_t ro = (uint32_t)((wn + nh * 32 + nb * 16 + rowSel) * 64);
                    const uint32_t ad = bb + BH_OFF + SWZ64(ro + kbyte);
                    uint32_t r[4];
                    ldmx4(r, ad);
                    bh[nb * 2][0] = r[0]; bh[nb * 2][1] = r[2];
                    bh[nb * 2 + 1][0] = r[1]; bh[nb * 2 + 1][1] = r[3];
                    if (NPASS == 3) {
                        uint32_t s[4];
                        ldmx4(s, ad + (BL_OFF - BH_OFF));
                        bl[nb * 2][0] = s[0]; bl[nb * 2][1] = s[2];
                        bl[nb * 2 + 1][0] = s[1]; bl[nb * 2 + 1][1] = s[3];
                    }
                }
                #pragma unroll
                for (int mf = 0; mf < 2; mf++)
                    #pragma unroll
                    for (int nf = 0; nf < 4; nf++) {
                        float* a4 = acc[mf][nh * 4 + nf];
                        mma_f16(a4, ah[mf], bh[nf]);
                        if (NPASS >= 2) mma_f16(a4, al[mf], bh[nf]);
                        if (NPASS == 3) mma_f16(a4, ah[mf], bl[nf]);
                    }
            }
        }
    }

    // epilogue
    const bool hasB = (bias != nullptr);
    #pragma unroll
    for (int mf = 0; mf < 2; mf++) {
        const int row = mBase + wm + mf * 16 + g;
        #pragma unroll
        for (int nf = 0; nf < 8; nf++) {
            const int col = nBase + wn + nf * 8 + 2 * tq;
            const float b0 = hasB ? bias[col] : 0.f;
            const float b1 = hasB ? bias[col + 1] : 0.f;
            if (HOUT) {
                __half* C = (__half*)Cout;
                *(__half2*)&C[(size_t)row * ldc + col] =
                    __floats2half2_rn(acc[mf][nf][0] + b0, acc[mf][nf][1] + b1);
                *(__half2*)&C[(size_t)(row + 8) * ldc + col] =
                    __floats2half2_rn(acc[mf][nf][2] + b0, acc[mf][nf][3] + b1);
            } else {
                float* C = (float*)Cout;
                *(float2*)&C[(size_t)row * ldc + col] =
                    make_float2(acc[mf][nf][0] + b0, acc[mf][nf][1] + b1);
                *(float2*)&C[(size_t)(row + 8) * ldc + col] =
                    make_float2(acc[mf][nf][2] + b0, acc[mf][nf][3] + b1);
            }
        }
    }
}

// ---------------------------------------------------------------------------
// Converters
// ---------------------------------------------------------------------------
// One launch for all three activations (z selects tensor).
__global__ __launch_bounds__(256)
void act_split_all(const float* __restrict__ X0, __half* __restrict__ Y0,
                   const float* __restrict__ X1, __half* __restrict__ Y1,
                   const float* __restrict__ X2, __half* __restrict__ Y2)
{
    const float* X = (blockIdx.z == 0) ? X0 : (blockIdx.z == 1) ? X1 : X2;
    __half*      Y = (blockIdx.z == 0) ? Y0 : (blockIdx.z == 1) ? Y1 : Y2;

    const int idx = blockIdx.x * 256 + threadIdx.x;  // one float4 of a 512-col row
    const int row = idx >> 7, c4 = idx & 127;
    const float4 v = ((const float4*)X)[idx];
    float f[4] = { v.x, v.y, v.z, v.w };
    __half h[4], l[4];
    #pragma unroll
    for (int i = 0; i < 4; i++) {
        h[i] = __float2half_rn(f[i]);
        l[i] = __float2half_rn(f[i] - __half2float(h[i]));
    }
    const size_t o = (size_t)row * 1024 + c4 * 4;
    __half2* ph = (__half2*)(Y + o);
    ph[0] = __halves2half2(h[0], h[1]);
    ph[1] = __halves2half2(h[2], h[3]);
    __half2* pl = (__half2*)(Y + o + DMODEL);
    pl[0] = __halves2half2(l[0], l[1]);
    pl[1] = __halves2half2(l[2], l[3]);
}

// Batched transpose+split for Wq/Wk/Wv (blockIdx.z selects tensor).
__global__ __launch_bounds__(256)
void wtrans_split_qkv(const float* __restrict__ W0, __half* __restrict__ Y0,
                      const float* __restrict__ W1, __half* __restrict__ Y1,
                      const float* __restrict__ W2, __half* __restrict__ Y2)
{
    const float* W = (blockIdx.z == 0) ? W0 : (blockIdx.z == 1) ? W1 : W2;
    __half*      Y = (blockIdx.z == 0) ? Y0 : (blockIdx.z == 1) ? Y1 : Y2;
    const int Kin = DMODEL, Nin = DHID, ldo = 2 * DMODEL;

    __shared__ float t[32][33];
    const int n  = blockIdx.x * 32 + threadIdx.x;
    const int k0 = blockIdx.y * 32;
    #pragma unroll
    for (int i = 0; i < 4; i++)
        t[threadIdx.y + i * 8][threadIdx.x] = W[(size_t)(k0 + threadIdx.y + i * 8) * Nin + n];
    __syncthreads();
    const int kc = k0 + threadIdx.x;
    #pragma unroll
    for (int i = 0; i < 4; i++) {
        const int nr = blockIdx.x * 32 + threadIdx.y + i * 8;
        const float v = t[threadIdx.x][threadIdx.y + i * 8];
        const __half hi = __float2half_rn(v);
        const __half lo = __float2half_rn(v - __half2float(hi));
        Y[(size_t)nr * ldo + kc]       = hi;
        Y[(size_t)nr * ldo + Kin + kc] = lo;
    }
}

// Transpose Wo [DHID, DMODEL] -> K-major fp16 hi only [DMODEL rows][DHID].
__global__ __launch_bounds__(256)
void wtrans_o(const float* __restrict__ W, __half* __restrict__ Y)
{
    const int Kin = DHID, Nin = DMODEL;
    __shared__ float t[32][33];
    const int n  = blockIdx.x * 32 + threadIdx.x;
    const int k0 = blockIdx.y * 32;
    #pragma unroll
    for (int i = 0; i < 4; i++)
        t[threadIdx.y + i * 8][threadIdx.x] = W[(size_t)(k0 + threadIdx.y + i * 8) * Nin + n];
    __syncthreads();
    const int kc = k0 + threadIdx.x;
    #pragma unroll
    for (int i = 0; i < 4; i++) {
        const int nr = blockIdx.x * 32 + threadIdx.y + i * 8;
        Y[(size_t)nr * Kin + kc] = __float2half_rn(t[threadIdx.x][threadIdx.y + i * 8]);
    }
}

// ---------------------------------------------------------------------------
// Per-token attention (8x8 over heads); V in fp16, AO out fp16.
// ---------------------------------------------------------------------------
__global__ __launch_bounds__(128)
void attn_kernel()
{
    const int n = blockIdx.x;
    const int tid = threadIdx.x;
    const size_t base = (size_t)n * DHID;

    __shared__ float red[4][64];
    __shared__ float Sf[64];
    __shared__ float P[64];

    float q[8][4], k[8][4];
    #pragma unroll
    for (int h = 0; h < 8; h++)
        #pragma unroll
        for (int j = 0; j < 4; j++) {
            const int d = tid + j * 128;
            q[h][j] = g_Q[base + h * DMODEL + d];
            k[h][j] = g_K[base + h * DMODEL + d];
        }

    float s[64];
    #pragma unroll
    for (int h = 0; h < 8; h++)
        #pragma unroll
        for (int gg = 0; gg < 8; gg++) {
            float a = 0.f;
            #pragma unroll
            for (int j = 0; j < 4; j++) a += q[h][j] * k[gg][j];
            s[h * 8 + gg] = a;
        }

    const int lane = tid & 31, w = tid >> 5;
    #pragma unroll
    for (int i = 0; i < 64; i++) {
        float v = s[i];
        v += __shfl_down_sync(0xffffffffu, v, 16);
        v += __shfl_down_sync(0xffffffffu, v, 8);
        v += __shfl_down_sync(0xffffffffu, v, 4);
        v += __shfl_down_sync(0xffffffffu, v, 2);
        v += __shfl_down_sync(0xffffffffu, v, 1);
        if (lane == 0) red[w][i] = v;
    }
    __syncthreads();
    if (tid < 64) Sf[tid] = red[0][tid] + red[1][tid] + red[2][tid] + red[3][tid];
    __syncthreads();
    if (tid < 8) {
        float m = -1e30f;
        #pragma unroll
        for (int gg = 0; gg < 8; gg++) m = fmaxf(m, Sf[tid * 8 + gg]);
        float e[8], sum = 0.f;
        #pragma unroll
        for (int gg = 0; gg < 8; gg++) { e[gg] = expf(Sf[tid * 8 + gg] - m); sum += e[gg]; }
        const float inv = 1.f / sum;
        #pragma unroll
        for (int gg = 0; gg < 8; gg++) P[tid * 8 + gg] = e[gg] * inv;
    }
    __syncthreads();

    float vv[8][4];
    #pragma unroll
    for (int h = 0; h < 8; h++)
        #pragma unroll
        for (int j = 0; j < 4; j++)
            vv[h][j] = __half2float(g_Vh[base + h * DMODEL + tid + j * 128]);

    #pragma unroll
    for (int h = 0; h < 8; h++) {
        #pragma unroll
        for (int j = 0; j < 4; j++) {
            float o = 0.f;
            #pragma unroll
            for (int gg = 0; gg < 8; gg++) o += P[h * 8 + gg] * vv[gg][j];
            g_AOh[base + h * DMODEL + tid + j * 128] = __float2half_rn(o);
        }
    }
}

// ---------------------------------------------------------------------------
// launch
// ---------------------------------------------------------------------------
extern "C" void kernel_launch(void* const* d_in, const int* in_sizes, int n_in,
                              void* d_out, int out_size)
{
    const float* queries = (const float*)d_in[0];
    const float* keys    = (const float*)d_in[1];
    const float* values  = (const float*)d_in[2];
    const float* Wq      = (const float*)d_in[3];
    const float* Wk      = (const float*)d_in[4];
    const float* Wv      = (const float*)d_in[5];
    const float* Wo      = (const float*)d_in[6];
    const float* bo      = (const float*)d_in[7];
    float* out = (float*)d_out;

    float *Qp, *Kp;
    __half *Vh, *Xq, *Xk, *Xv, *Wqs, *Wks, *Wvs, *Woh, *AOh;
    cudaGetSymbolAddress((void**)&Qp,  g_Q);
    cudaGetSymbolAddress((void**)&Kp,  g_K);
    cudaGetSymbolAddress((void**)&Vh,  g_Vh);
    cudaGetSymbolAddress((void**)&Xq,  g_Xq);
    cudaGetSymbolAddress((void**)&Xk,  g_Xk);
    cudaGetSymbolAddress((void**)&Xv,  g_Xv);
    cudaGetSymbolAddress((void**)&Wqs, g_Wqs);
    cudaGetSymbolAddress((void**)&Wks, g_Wks);
    cudaGetSymbolAddress((void**)&Wvs, g_Wvs);
    cudaGetSymbolAddress((void**)&Woh, g_Woh);
    cudaGetSymbolAddress((void**)&AOh, g_AOh);

    const int SM3 = 1024 + NSTAGE * 4 * OPTILE;  // 97.3 KB -> 2 CTAs/SM
    const int SM1 = 1024 + NSTAGE * 2 * OPTILE;  // 49.2 KB -> 2 CTAs/SM
    cudaFuncSetAttribute((const void*)gemm_split_hmma<3, false>,
                         cudaFuncAttributeMaxDynamicSharedMemorySize, SM3);
    cudaFuncSetAttribute((const void*)gemm_split_hmma<1, true>,
                         cudaFuncAttributeMaxDynamicSharedMemorySize, SM1);
    cudaFuncSetAttribute((const void*)gemm_split_hmma<1, false>,
                         cudaFuncAttributeMaxDynamicSharedMemorySize, SM1);

    // 1) split converts (3 launches total)
    act_split_all<<<dim3(16384, 1, 3), 256>>>(queries, Xq, keys, Xk, values, Xv);
    wtrans_split_qkv<<<dim3(DHID / 32, DMODEL / 32, 3), dim3(32, 8)>>>(
        Wq, Wqs, Wk, Wks, Wv, Wvs);
    wtrans_o<<<dim3(DMODEL / 32, DHID / 32), dim3(32, 8)>>>(Wo, Woh);

    // 2) projections: Q,K 3-pass fp32-out; V 1-pass fp16-out
    dim3 gProj(DHID / 128, NTOK / 128);   // (32, 256)
    gemm_split_hmma<3, false><<<gProj, 256, SM3>>>(Xq, 2 * DMODEL, DMODEL,
                                                   Wqs, 2 * DMODEL, DMODEL,
                                                   Qp, DHID, nullptr, DMODEL / 32);
    gemm_split_hmma<3, false><<<gProj, 256, SM3>>>(Xk, 2 * DMODEL, DMODEL,
                                                   Wks, 2 * DMODEL, DMODEL,
                                                   Kp, DHID, nullptr, DMODEL / 32);
    gemm_split_hmma<1, true><<<gProj, 256, SM1>>>(Xv, 2 * DMODEL, 0,
                                                  Wvs, 2 * DMODEL, 0,
                                                  Vh, DHID, nullptr, DMODEL / 32);

    // 3) per-token attention (V fp16) -> fp16 AO
    attn_kernel<<<NTOK, 128>>>();

    // 4) output projection + bias: 1-pass, packed hi-only Wo (ldb = DHID)
    dim3 gOut(DMODEL / 128, NTOK / 128);  // (4, 256)
    gemm_split_hmma<1, false><<<gOut, 256, SM1>>>(AOh, DHID, 0,
                                                  Woh, DHID, 0,
                                                  out, DMODEL, bo, DHID / 32);
}